// round 14
// baseline (speedup 1.0000x reference)
#include <cuda_runtime.h>
#include <cuda_bf16.h>
#include <cuda_fp16.h>
#include <cstdint>

#define Bsz 64
#define T   256
#define Isz 2048
#define Hsz 4096
#define Osz 1024

#define THRESHOLD 1.0f
#define DECAY     0.9f
#define SCL   512.0f
#define ISCL  (1.0f / 512.0f)

// ---------------- scratch (device globals; no allocation allowed) ----------
__device__ __nv_bfloat16 g_Ahi[T * Isz];       // 1 MB   bf16 main A
__device__ __nv_bfloat16 g_Bhi[Hsz * Isz];     // 16 MB  bf16 main B [N][K]
__device__ __half        g_A2[T * 2 * Isz];    // 2 MB   fp16: [k]=512*Alo, [2048+k]=A
__device__ __half        g_B2[Hsz * 2 * Isz];  // 32 MB  fp16: [k]=Bhi,     [2048+k]=512*Blo
__device__ float g_cur[T * Hsz];               // 4 MB
__device__ float g_agg[Hsz];

// ---------------- PTX helpers ----------------------------------------------
__device__ __forceinline__ uint32_t smem_u32(const void* p) {
    uint32_t a;
    asm("{ .reg .u64 t; cvta.to.shared.u64 t, %1; cvt.u32.u64 %0, t; }"
        : "=r"(a) : "l"(p));
    return a;
}
__device__ __forceinline__ void cp16(uint32_t dst, const void* src) {
    asm volatile("cp.async.cg.shared.global [%0], [%1], 16;" :: "r"(dst), "l"(src));
}
__device__ __forceinline__ void cp_commit() {
    asm volatile("cp.async.commit_group;" ::: "memory");
}
template <int N> __device__ __forceinline__ void cp_wait() {
    asm volatile("cp.async.wait_group %0;" :: "n"(N) : "memory");
}
#define LDSM_X4(r0, r1, r2, r3, addr) \
    asm volatile("ldmatrix.sync.aligned.m8n8.x4.shared.b16 {%0,%1,%2,%3}, [%4];" \
                 : "=r"(r0), "=r"(r1), "=r"(r2), "=r"(r3) : "r"(addr))
#define MMA_BF16(d, a, b0, b1) \
    asm volatile("mma.sync.aligned.m16n8k16.row.col.f32.bf16.bf16.f32 " \
                 "{%0,%1,%2,%3}, {%4,%5,%6,%7}, {%8,%9}, {%0,%1,%2,%3};" \
                 : "+f"((d)[0]), "+f"((d)[1]), "+f"((d)[2]), "+f"((d)[3]) \
                 : "r"((a)[0]), "r"((a)[1]), "r"((a)[2]), "r"((a)[3]), \
                   "r"(b0), "r"(b1))
#define MMA_F16(d, a, b0, b1) \
    asm volatile("mma.sync.aligned.m16n8k16.row.col.f16.f16.f16.f16 " \
                 "{%0,%1}, {%2,%3,%4,%5}, {%6,%7}, {%0,%1};" \
                 : "+r"((d)[0]), "+r"((d)[1]) \
                 : "r"((a)[0]), "r"((a)[1]), "r"((a)[2]), "r"((a)[3]), \
                   "r"(b0), "r"(b1))

// ---------------------------------------------------------------------------
// 1) Merged prep: blocks [0,512) batch-reduce x -> Ahi/A2;
//    blocks [512, 512+4096) transpose+convert W_in -> Bhi/B2.
// ---------------------------------------------------------------------------
#define RED_BLOCKS 512
__global__ __launch_bounds__(256) void prep_kernel(const float* __restrict__ x,
                                                   const float* __restrict__ W) {
    if (blockIdx.x < RED_BLOCKS) {
        const int idx = blockIdx.x * 256 + threadIdx.x;  // over T*I/4
        const int n4  = (T * Isz) / 4;
        const float4* __restrict__ x4 = reinterpret_cast<const float4*>(x);
        float a[4] = {0.f, 0.f, 0.f, 0.f};
#pragma unroll 16
        for (int b = 0; b < Bsz; ++b) {
            float4 v = x4[(size_t)b * n4 + idx];
            a[0] += v.x; a[1] += v.y; a[2] += v.z; a[3] += v.w;
        }
        const float s = 1.0f / (float)Bsz;
        const int base = idx * 4;
        const int t = base >> 11;
        const int k = base & 2047;
#pragma unroll
        for (int i = 0; i < 4; ++i) {
            const float v = a[i] * s;
            const __nv_bfloat16 hi = __float2bfloat16(v);
            const float hif = __bfloat162float(hi);
            g_Ahi[base + i] = hi;
            g_A2[(size_t)t * 4096 + k + i]        = __float2half_rn((v - hif) * SCL);
            g_A2[(size_t)t * 4096 + 2048 + k + i] = __float2half_rn(v);
        }
    } else {
        __shared__ float s[64][33];
        const int bid = blockIdx.x - RED_BLOCKS;       // 0..4095
        const int h0 = (bid & 127) * 32;
        const int i0 = (bid >> 7) * 64;
        const int tc = threadIdx.x & 31;
        const int tr = threadIdx.x >> 5;               // 0..7
#pragma unroll
        for (int j = 0; j < 8; ++j) {
            const int r = tr + j * 8;
            s[r][tc] = W[(size_t)(i0 + r) * Hsz + h0 + tc];
        }
        __syncthreads();
#pragma unroll
        for (int j = 0; j < 4; ++j) {
            const int hl = tr + j * 8;
            const float v0 = s[2 * tc][hl];
            const float v1 = s[2 * tc + 1][hl];
            const __nv_bfloat16 h0b = __float2bfloat16(v0);
            const __nv_bfloat16 h1b = __float2bfloat16(v1);
            const float h0f = __bfloat162float(h0b);
            const float h1f = __bfloat162float(h1b);
            // bf16 main
            const uint32_t hp = (uint32_t)__bfloat16_as_ushort(h0b) |
                                ((uint32_t)__bfloat16_as_ushort(h1b) << 16);
            // fp16 copies of Bhi (exact) and scaled residuals
            const __half a0 = __float2half_rn(h0f);
            const __half a1 = __float2half_rn(h1f);
            const __half c0 = __float2half_rn((v0 - h0f) * SCL);
            const __half c1 = __float2half_rn((v1 - h1f) * SCL);
            const uint32_t pa = (uint32_t)__half_as_ushort(a0) |
                                ((uint32_t)__half_as_ushort(a1) << 16);
            const uint32_t pb = (uint32_t)__half_as_ushort(c0) |
                                ((uint32_t)__half_as_ushort(c1) << 16);
            const size_t oh = ((size_t)(h0 + hl) * Isz + i0) / 2 + tc;
            const size_t o2 = ((size_t)(h0 + hl) * 4096 + i0) / 2 + tc;
            reinterpret_cast<uint32_t*>(g_Bhi)[o2 * 0 + oh] = hp;
            reinterpret_cast<uint32_t*>(g_B2)[o2] = pa;
            reinterpret_cast<uint32_t*>(g_B2)[o2 + 1024] = pb;   // +2048 halves
        }
    }
}

// ---------------------------------------------------------------------------
// 2) Mixed-rate HMMA GEMM:
//    acc(f32)  += Ahi(bf16) * Bhi(bf16)                      [rt 16]
//    acc16(f16)+= 512*Alo(f16)*Bhi(f16) + A(f16)*512*Blo(f16) [rt 8?]
//    flush acc += acc16/512 every 2 k16 steps.
//    CTA 64x128, 8 warps, BK=64, 2-stage cp.async, 1 barrier/chunk.
// ---------------------------------------------------------------------------
#define LDA_B 144                        // 64 el (128B) + 16B pad
#define AHI_OFF 0
#define BHI_OFF 9216
#define A2A_OFF 27648
#define A2B_OFF 36864
#define B2A_OFF 46080
#define B2B_OFF 64512
#define STAGE_B 82944
#define NSTAGE 2
#define GEMM_SMEM (NSTAGE * STAGE_B)     // 165888
#define NCHUNK 32                        // 2048 / 64

__global__ __launch_bounds__(256, 1) void gemm_hmma(const float* __restrict__ b_in) {
    extern __shared__ char smem[];
    const uint32_t sb = smem_u32(smem);
    const int tid  = threadIdx.x;
    const int lane = tid & 31;
    const int wid  = tid >> 5;
    const int m0 = blockIdx.y * 64;
    const int n0 = blockIdx.x * 128;

    const int wm_off = (wid & 1) * 32;
    const int wn_off = (wid >> 1) * 32;

    float acc[2][4][4];
    uint32_t acc16[2][4][2];
#pragma unroll
    for (int i = 0; i < 2; ++i)
#pragma unroll
        for (int j = 0; j < 4; ++j) {
#pragma unroll
            for (int k = 0; k < 4; ++k) acc[i][j][k] = 0.f;
            acc16[i][j][0] = 0; acc16[i][j][1] = 0;
        }

    auto stage_base = [&](int c) -> uint32_t {
        return sb + (uint32_t)(c & 1) * STAGE_B;
    };

    auto load_chunk = [&](int c) {
        const int k0 = c << 6;
        const uint32_t base = stage_base(c);
#pragma unroll
        for (int i = 0; i < 2; ++i) {
            const int idx = i * 256 + tid;
            const int row = idx >> 3, cc = idx & 7;
            const uint32_t so = row * LDA_B + cc * 16;
            cp16(base + AHI_OFF + so, &g_Ahi[(size_t)(m0 + row) * Isz + k0 + cc * 8]);
            cp16(base + A2A_OFF + so, &g_A2[(size_t)(m0 + row) * 4096 + k0 + cc * 8]);
            cp16(base + A2B_OFF + so, &g_A2[(size_t)(m0 + row) * 4096 + 2048 + k0 + cc * 8]);
        }
#pragma unroll
        for (int i = 0; i < 4; ++i) {
            const int idx = i * 256 + tid;
            const int row = idx >> 3, cc = idx & 7;
            const uint32_t so = row * LDA_B + cc * 16;
            cp16(base + BHI_OFF + so, &g_Bhi[(size_t)(n0 + row) * Isz + k0 + cc * 8]);
            cp16(base + B2A_OFF + so, &g_B2[(size_t)(n0 + row) * 4096 + k0 + cc * 8]);
            cp16(base + B2B_OFF + so, &g_B2[(size_t)(n0 + row) * 4096 + 2048 + k0 + cc * 8]);
        }
        cp_commit();
    };

    const uint32_t a_row_off = (uint32_t)(wm_off + (lane & 15)) * LDA_B;
    const uint32_t b_row_off = (uint32_t)(wn_off + (lane & 15)) * LDA_B;
    const uint32_t k_half    = (uint32_t)((lane >> 4) << 3) * 2;

    auto flush16 = [&]() {
#pragma unroll
        for (int mt = 0; mt < 2; ++mt)
#pragma unroll
            for (int nt = 0; nt < 4; ++nt) {
                const __half2 h0 = *reinterpret_cast<__half2*>(&acc16[mt][nt][0]);
                const __half2 h1 = *reinterpret_cast<__half2*>(&acc16[mt][nt][1]);
                const float2 f0 = __half22float2(h0);
                const float2 f1 = __half22float2(h1);
                acc[mt][nt][0] += f0.x * ISCL;
                acc[mt][nt][1] += f0.y * ISCL;
                acc[mt][nt][2] += f1.x * ISCL;
                acc[mt][nt][3] += f1.y * ISCL;
                acc16[mt][nt][0] = 0; acc16[mt][nt][1] = 0;
            }
    };

    load_chunk(0);

    for (int j = 0; j < NCHUNK; ++j) {
        cp_wait<0>();
        __syncthreads();
        if (j + 1 < NCHUNK) load_chunk(j + 1);

        const uint32_t base = stage_base(j);
#pragma unroll
        for (int k16 = 0; k16 < 4; ++k16) {
            const uint32_t kbyte = (uint32_t)(k16 * 16) * 2 + k_half;
            const uint32_t ar = a_row_off + kbyte;
            const uint32_t br = b_row_off + kbyte;
            uint32_t ahi[2][4], a2a[2][4], a2b[2][4];
            uint32_t bhi[2][4], b2a[2][4], b2b[2][4];
#pragma unroll
            for (int mt = 0; mt < 2; ++mt) {
                const uint32_t ro = ar + mt * 16 * LDA_B;
                LDSM_X4(ahi[mt][0], ahi[mt][1], ahi[mt][2], ahi[mt][3],
                        base + AHI_OFF + ro);
                LDSM_X4(a2a[mt][0], a2a[mt][1], a2a[mt][2], a2a[mt][3],
                        base + A2A_OFF + ro);
                LDSM_X4(a2b[mt][0], a2b[mt][1], a2b[mt][2], a2b[mt][3],
                        base + A2B_OFF + ro);
            }
#pragma unroll
            for (int nt2 = 0; nt2 < 2; ++nt2) {
                const uint32_t ro = br + nt2 * 16 * LDA_B;
                LDSM_X4(bhi[nt2][0], bhi[nt2][1], bhi[nt2][2], bhi[nt2][3],
                        base + BHI_OFF + ro);
                LDSM_X4(b2a[nt2][0], b2a[nt2][1], b2a[nt2][2], b2a[nt2][3],
                        base + B2A_OFF + ro);
                LDSM_X4(b2b[nt2][0], b2b[nt2][1], b2b[nt2][2], b2b[nt2][3],
                        base + B2B_OFF + ro);
            }
#pragma unroll
            for (int mt = 0; mt < 2; ++mt)
#pragma unroll
                for (int nt = 0; nt < 4; ++nt) {
                    const int g = nt >> 1, w = nt & 1;
                    MMA_BF16(acc[mt][nt], ahi[mt], bhi[g][w], bhi[g][2 + w]);
                    MMA_F16(acc16[mt][nt], a2a[mt], b2a[g][w], b2a[g][2 + w]);
                    MMA_F16(acc16[mt][nt], a2b[mt], b2b[g][w], b2b[g][2 + w]);
                }
            if (k16 & 1) flush16();
        }
    }

    // epilogue: write g_cur with bias
#pragma unroll
    for (int mt = 0; mt < 2; ++mt) {
#pragma unroll
        for (int nt = 0; nt < 4; ++nt) {
            const int col = n0 + wn_off + nt * 8 + (lane & 3) * 2;
            const float2 bia = *reinterpret_cast<const float2*>(&b_in[col]);
            const int r0 = m0 + wm_off + mt * 16 + (lane >> 2);
            float2 v0, v1;
            v0.x = acc[mt][nt][0] + bia.x;
            v0.y = acc[mt][nt][1] + bia.y;
            v1.x = acc[mt][nt][2] + bia.x;
            v1.y = acc[mt][nt][3] + bia.y;
            *reinterpret_cast<float2*>(&g_cur[(size_t)r0 * Hsz + col]) = v0;
            *reinterpret_cast<float2*>(&g_cur[(size_t)(r0 + 8) * Hsz + col]) = v1;
        }
    }
}

// ---------------------------------------------------------------------------
// 3) LIF scan: 128 blocks x 32 threads, software-pipelined 16-deep prefetch.
//    Also initializes out[] = b_out[] (blocks 0..31) ahead of the GEMV.
// ---------------------------------------------------------------------------
__global__ __launch_bounds__(32) void scan_kernel(const float* __restrict__ m0,
                                                  float* __restrict__ out,
                                                  const float* __restrict__ b_out) {
    const int h = blockIdx.x * 32 + threadIdx.x;
    if (blockIdx.x < Osz / 32) out[h] = b_out[h];

    float m = m0[h];
    float s = 0.f;
    float buf[2][16];
#pragma unroll
    for (int i = 0; i < 16; ++i)
        buf[0][i] = __ldg(&g_cur[(size_t)i * Hsz + h]);

#pragma unroll
    for (int t0 = 0; t0 < T; t0 += 16) {
        const int cur = (t0 >> 4) & 1;
        const int nxt = cur ^ 1;
        if (t0 + 16 < T) {
#pragma unroll
            for (int i = 0; i < 16; ++i)
                buf[nxt][i] = __ldg(&g_cur[(size_t)(t0 + 16 + i) * Hsz + h]);
        }
#pragma unroll
        for (int i = 0; i < 16; ++i) {
            m = DECAY * m + buf[cur][i];
            if (m > THRESHOLD) { s += 1.0f; m = 0.0f; }
        }
    }
    g_agg[h] = s * (1.0f / (float)T);
}

// ---------------------------------------------------------------------------
// 4) Output GEMV (out pre-initialized with bias by scan_kernel)
// ---------------------------------------------------------------------------
#define OUT_OB 128
#define OUT_HB 64

__global__ __launch_bounds__(OUT_OB) void out_gemv_kernel(
    const float* __restrict__ W_out, float* __restrict__ out)
{
    __shared__ float s_agg[OUT_HB];
    const int obase = blockIdx.x * OUT_OB;
    const int hbase = blockIdx.y * OUT_HB;
    const int tid   = threadIdx.x;

    if (tid < OUT_HB) s_agg[tid] = g_agg[hbase + tid];
    __syncthreads();

    const int o = obase + tid;
    const float* __restrict__ Wp = &W_out[(size_t)hbase * Osz + o];
    float acc0 = 0.f, acc1 = 0.f;
#pragma unroll
    for (int hh = 0; hh < OUT_HB; hh += 2) {
        acc0 += s_agg[hh]     * Wp[(size_t)hh * Osz];
        acc1 += s_agg[hh + 1] * Wp[(size_t)(hh + 1) * Osz];
    }
    atomicAdd(&out[o], acc0 + acc1);
}

// ---------------------------------------------------------------------------
extern "C" void kernel_launch(void* const* d_in, const int* in_sizes, int n_in,
                              void* d_out, int out_size) {
    const float* x     = (const float*)d_in[0];  // [B,T,I]
    const float* W_in  = (const float*)d_in[1];  // [I,H]
    const float* b_in  = (const float*)d_in[2];  // [H]
    const float* W_out = (const float*)d_in[3];  // [H,O]
    const float* b_out = (const float*)d_in[4];  // [O]
    const float* m0    = (const float*)d_in[5];  // [H]
    float* out = (float*)d_out;                  // [O]

    // 1) merged reduce + transpose/convert
    prep_kernel<<<RED_BLOCKS + (Hsz / 32) * (Isz / 64), 256>>>(x, W_in);

    // 2) mixed-rate HMMA GEMM: grid (32, 4) = 128 CTAs
    cudaFuncSetAttribute(gemm_hmma,
                         cudaFuncAttributeMaxDynamicSharedMemorySize,
                         GEMM_SMEM);
    dim3 gg(Hsz / 128, T / 64);
    gemm_hmma<<<gg, 256, GEMM_SMEM>>>(b_in);

    // 3) scan (+ output bias init): 128 blocks x 32 threads
    scan_kernel<<<Hsz / 32, 32>>>(m0, out, b_out);

    // 4) output GEMV: grid (8, 64) = 512 blocks
    dim3 g4(Osz / OUT_OB, Hsz / OUT_HB);
    out_gemv_kernel<<<g4, OUT_OB>>>(W_out, out);
}